// round 1
// baseline (speedup 1.0000x reference)
#include <cuda_runtime.h>
#include <math.h>

#define BATCH 2
#define SEQ   2048
#define DE    1024
#define DATT  1024
#define NH    16
#define DH    64
#define TRIPLE (3*DATT)
#define MROWS (BATCH*SEQ)   /* 4096 */

// Scratch (device globals: allocation-free per harness rules)
__device__ float g_qkv[(size_t)BATCH * SEQ * TRIPLE];   // (b, s, 3*d_att)
__device__ float g_attn[(size_t)BATCH * SEQ * DATT];    // (b, s, h*64+d)

// ---------------------------------------------------------------------------
// SGEMM + bias: C[M,N] = A[M,K] @ B[K,N] + bias[N]
// 128x128 tile, BK=8, 256 threads, 8x8 per-thread microtile.
// M,N multiples of 128; K multiple of 8 (true for all calls here).
// ---------------------------------------------------------------------------
__global__ __launch_bounds__(256) void sgemm_bias(
    const float* __restrict__ A, const float* __restrict__ Bm,
    const float* __restrict__ bias, float* __restrict__ C,
    int M, int N, int K)
{
    __shared__ float As[8][132];   // padded: conflict-free transposed store
    __shared__ float Bs[8][128];

    const int tid = threadIdx.x;
    const int tx = tid & 15;
    const int ty = tid >> 4;
    const int bm = blockIdx.y * 128;
    const int bn = blockIdx.x * 128;

    const int a_m = tid >> 1;          // 0..127
    const int a_k = (tid & 1) * 4;     // 0 or 4
    const int b_k = tid >> 5;          // 0..7
    const int b_n = (tid & 31) * 4;    // 0..124

    float acc[8][8];
#pragma unroll
    for (int i = 0; i < 8; i++)
#pragma unroll
        for (int j = 0; j < 8; j++) acc[i][j] = 0.0f;

    const float* Aptr = A + (size_t)(bm + a_m) * K + a_k;
    const float* Bptr = Bm + (size_t)b_k * N + bn + b_n;

    for (int k0 = 0; k0 < K; k0 += 8) {
        float4 av = *(const float4*)(Aptr + k0);
        As[a_k + 0][a_m] = av.x;
        As[a_k + 1][a_m] = av.y;
        As[a_k + 2][a_m] = av.z;
        As[a_k + 3][a_m] = av.w;
        float4 bv = *(const float4*)(Bptr + (size_t)k0 * N);
        *(float4*)&Bs[b_k][b_n] = bv;
        __syncthreads();

#pragma unroll
        for (int kk = 0; kk < 8; kk++) {
            float4 a0 = *(const float4*)&As[kk][ty * 8];
            float4 a1 = *(const float4*)&As[kk][ty * 8 + 4];
            float4 b0 = *(const float4*)&Bs[kk][tx * 8];
            float4 b1 = *(const float4*)&Bs[kk][tx * 8 + 4];
            float ar[8] = {a0.x, a0.y, a0.z, a0.w, a1.x, a1.y, a1.z, a1.w};
            float br[8] = {b0.x, b0.y, b0.z, b0.w, b1.x, b1.y, b1.z, b1.w};
#pragma unroll
            for (int i = 0; i < 8; i++)
#pragma unroll
                for (int j = 0; j < 8; j++)
                    acc[i][j] += ar[i] * br[j];
        }
        __syncthreads();
    }

#pragma unroll
    for (int i = 0; i < 8; i++) {
        const int row = bm + ty * 8 + i;
#pragma unroll
        for (int j = 0; j < 8; j++) {
            const int col = bn + tx * 8 + j;
            C[(size_t)row * N + col] = acc[i][j] + bias[col];
        }
    }
}

// ---------------------------------------------------------------------------
// Flash-style attention, fp32. Block = 64 queries x one head x one batch.
// Key tiles of 32. 256 threads: (ty,tx) in 16x16; each thread owns
// 4 query rows (scores: 4q x 2k; output: 4q x 4d) with online softmax.
// ---------------------------------------------------------------------------
__global__ __launch_bounds__(256) void attn64(const float* __restrict__ qkv,
                                              float* __restrict__ out)
{
    __shared__ float Qs[64][68];    // padded stride 68 -> aligned float4 rows
    __shared__ float KsT[64][33];   // [d][k], conflict-free scalar reads
    __shared__ float Vs[32][64];    // float4 reads
    __shared__ float Ps[64][33];

    const int tid = threadIdx.x;
    const int tx = tid & 15;
    const int ty = tid >> 4;

    const int qblk = blockIdx.x;        // 0..31
    const int h    = blockIdx.y;        // 0..15
    const int b    = blockIdx.z;        // 0..1
    const int q0   = qblk * 64;

    const float* base = qkv + (size_t)b * SEQ * TRIPLE;
    const float* Qg = base + h * DH;             // + s*TRIPLE + d
    const float* Kg = base + DATT + h * DH;
    const float* Vg = base + 2 * DATT + h * DH;

    // Load Q tile
    for (int idx = tid; idx < 64 * 64; idx += 256) {
        int r = idx >> 6, c = idx & 63;
        Qs[r][c] = Qg[(size_t)(q0 + r) * TRIPLE + c];
    }

    float m[4], l[4], acc[4][4];
#pragma unroll
    for (int i = 0; i < 4; i++) {
        m[i] = -1e30f;
        l[i] = 0.0f;
#pragma unroll
        for (int j = 0; j < 4; j++) acc[i][j] = 0.0f;
    }
    __syncthreads();

    const float scale = 0.125f;   // 1/sqrt(64)

    for (int k0 = 0; k0 < SEQ; k0 += 32) {
        // Load K (transposed) and V tiles
        for (int idx = tid; idx < 32 * 64; idx += 256) {
            int kk = idx >> 6, d = idx & 63;
            float kval = Kg[(size_t)(k0 + kk) * TRIPLE + d];
            float vval = Vg[(size_t)(k0 + kk) * TRIPLE + d];
            KsT[d][kk] = kval;
            Vs[kk][d]  = vval;
        }
        __syncthreads();

        // Scores: s[i][j] for q=ty*4+i, k=tx*2+j
        float s[4][2];
#pragma unroll
        for (int i = 0; i < 4; i++) { s[i][0] = 0.0f; s[i][1] = 0.0f; }

#pragma unroll 4
        for (int d = 0; d < 64; d += 4) {
            float4 qv[4];
#pragma unroll
            for (int i = 0; i < 4; i++)
                qv[i] = *(const float4*)&Qs[ty * 4 + i][d];
            float ka0 = KsT[d + 0][tx * 2], kb0 = KsT[d + 0][tx * 2 + 1];
            float ka1 = KsT[d + 1][tx * 2], kb1 = KsT[d + 1][tx * 2 + 1];
            float ka2 = KsT[d + 2][tx * 2], kb2 = KsT[d + 2][tx * 2 + 1];
            float ka3 = KsT[d + 3][tx * 2], kb3 = KsT[d + 3][tx * 2 + 1];
#pragma unroll
            for (int i = 0; i < 4; i++) {
                s[i][0] += qv[i].x * ka0 + qv[i].y * ka1 + qv[i].z * ka2 + qv[i].w * ka3;
                s[i][1] += qv[i].x * kb0 + qv[i].y * kb1 + qv[i].z * kb2 + qv[i].w * kb3;
            }
        }

        // Online softmax update
        float rmax[4];
#pragma unroll
        for (int i = 0; i < 4; i++) {
            s[i][0] *= scale; s[i][1] *= scale;
            rmax[i] = fmaxf(s[i][0], s[i][1]);
        }
#pragma unroll
        for (int off = 8; off >= 1; off >>= 1)
#pragma unroll
            for (int i = 0; i < 4; i++)
                rmax[i] = fmaxf(rmax[i], __shfl_xor_sync(0xffffffffu, rmax[i], off));

        float alpha[4], p[4][2], rsum[4];
#pragma unroll
        for (int i = 0; i < 4; i++) {
            float mnew = fmaxf(m[i], rmax[i]);
            alpha[i] = __expf(m[i] - mnew);
            m[i] = mnew;
            p[i][0] = __expf(s[i][0] - mnew);
            p[i][1] = __expf(s[i][1] - mnew);
            rsum[i] = p[i][0] + p[i][1];
        }
#pragma unroll
        for (int off = 8; off >= 1; off >>= 1)
#pragma unroll
            for (int i = 0; i < 4; i++)
                rsum[i] += __shfl_xor_sync(0xffffffffu, rsum[i], off);
#pragma unroll
        for (int i = 0; i < 4; i++) {
            l[i] = l[i] * alpha[i] + rsum[i];
#pragma unroll
            for (int j = 0; j < 4; j++) acc[i][j] *= alpha[i];
            Ps[ty * 4 + i][tx * 2]     = p[i][0];
            Ps[ty * 4 + i][tx * 2 + 1] = p[i][1];
        }
        __syncthreads();

        // acc += P @ V  (4q x 4d, sum over 32 keys)
#pragma unroll 8
        for (int kk = 0; kk < 32; kk++) {
            float4 v = *(const float4*)&Vs[kk][tx * 4];
#pragma unroll
            for (int i = 0; i < 4; i++) {
                float pv = Ps[ty * 4 + i][kk];
                acc[i][0] += pv * v.x;
                acc[i][1] += pv * v.y;
                acc[i][2] += pv * v.z;
                acc[i][3] += pv * v.w;
            }
        }
        __syncthreads();
    }

    // Write (b, s, h*64+d)
#pragma unroll
    for (int i = 0; i < 4; i++) {
        const float inv_l = 1.0f / l[i];
        const size_t row = (size_t)b * SEQ + q0 + ty * 4 + i;
#pragma unroll
        for (int j = 0; j < 4; j++)
            out[row * DATT + h * DH + tx * 4 + j] = acc[i][j] * inv_l;
    }
}

// ---------------------------------------------------------------------------
extern "C" void kernel_launch(void* const* d_in, const int* in_sizes, int n_in,
                              void* d_out, int out_size)
{
    const float* x     = (const float*)d_in[0];
    const float* w_in  = (const float*)d_in[1];
    const float* b_in  = (const float*)d_in[2];
    const float* w_out = (const float*)d_in[3];
    const float* b_out = (const float*)d_in[4];
    float* out = (float*)d_out;

    float* qkv = nullptr;
    float* attn = nullptr;
    cudaGetSymbolAddress((void**)&qkv, g_qkv);
    cudaGetSymbolAddress((void**)&attn, g_attn);

    // 1) QKV = x @ w_in + b_in   (4096 x 3072 x 1024)
    dim3 g1(TRIPLE / 128, MROWS / 128);
    sgemm_bias<<<g1, 256>>>(x, w_in, b_in, qkv, MROWS, TRIPLE, DE);

    // 2) attention
    dim3 g2(SEQ / 64, NH, BATCH);
    attn64<<<g2, 256>>>(qkv, attn);

    // 3) out = attn @ w_out + b_out   (4096 x 1024 x 1024)
    dim3 g3(DATT / 128, MROWS / 128);
    sgemm_bias<<<g3, 256>>>(attn, w_out, b_out, out, MROWS, DE, DATT);
}

// round 2
// speedup vs baseline: 3.3392x; 3.3392x over previous
#include <cuda_runtime.h>
#include <math.h>
#include <stdint.h>

#define BATCH 2
#define SEQ   2048
#define DE    1024
#define DATT  1024
#define NH    16
#define DH    64
#define TRIPLE (3*DATT)
#define MROWS (BATCH*SEQ)   /* 4096 */

// Scratch (device globals: allocation-free per harness rules)
__device__ float g_qkv[(size_t)BATCH * SEQ * TRIPLE];   // (b, s, 3*d_att)
__device__ float g_attn[(size_t)BATCH * SEQ * DATT];    // (b, s, h*64+d)

__device__ __forceinline__ uint32_t f2tf32(float f) {
    uint32_t u;
    asm("cvt.rna.tf32.f32 %0, %1;" : "=r"(u) : "f"(f));
    return u;
}

__device__ __forceinline__ void mma_tf32(float* d, const uint32_t* a, const uint32_t* b) {
    asm volatile(
        "mma.sync.aligned.m16n8k8.row.col.f32.tf32.tf32.f32 "
        "{%0,%1,%2,%3}, {%4,%5,%6,%7}, {%8,%9}, {%0,%1,%2,%3};\n"
        : "+f"(d[0]), "+f"(d[1]), "+f"(d[2]), "+f"(d[3])
        : "r"(a[0]), "r"(a[1]), "r"(a[2]), "r"(a[3]), "r"(b[0]), "r"(b[1]));
}

// ---------------------------------------------------------------------------
// TF32 GEMM + bias: C[M,N] = A[M,K] @ B[K,N] + bias[N]
// CTA 128x128, BK=32, 8 warps (2x4), warp tile 64x32, mma m16n8k8.
// ---------------------------------------------------------------------------
__global__ __launch_bounds__(256) void gemm_tf32_bias(
    const float* __restrict__ A, const float* __restrict__ B,
    const float* __restrict__ bias, float* __restrict__ C,
    int M, int N, int K)
{
    __shared__ __align__(16) uint32_t As[128][36];   // [m][k], stride 36 (=4 mod 32)
    __shared__ __align__(16) uint32_t Bs[32][136];   // [k][n], stride 136 (=8 mod 32)

    const int tid  = threadIdx.x;
    const int lane = tid & 31;
    const int warp = tid >> 5;
    const int wm = warp >> 2;        // 0..1
    const int wn = warp & 3;         // 0..3
    const int g  = lane >> 2;        // groupID 0..7
    const int t  = lane & 3;         // threadID_in_group 0..3
    const int bm = blockIdx.y * 128;
    const int bn = blockIdx.x * 128;

    float acc[4][4][4] = {};         // [mf][nf][reg]

    for (int k0 = 0; k0 < K; k0 += 32) {
        // Load A tile (coalesced float4 along K, row-major store, cvt to tf32)
#pragma unroll
        for (int i = 0; i < 4; i++) {
            int idx = tid + i * 256;
            int m = idx >> 3, k4 = (idx & 7) * 4;
            float4 v = *(const float4*)(A + (size_t)(bm + m) * K + k0 + k4);
            uint4 w = make_uint4(f2tf32(v.x), f2tf32(v.y), f2tf32(v.z), f2tf32(v.w));
            *(uint4*)&As[m][k4] = w;
        }
        // Load B tile (coalesced float4 along N)
#pragma unroll
        for (int i = 0; i < 4; i++) {
            int idx = tid + i * 256;
            int k = idx >> 5, n4 = (idx & 31) * 4;
            float4 v = *(const float4*)(B + (size_t)(k0 + k) * N + bn + n4);
            uint4 w = make_uint4(f2tf32(v.x), f2tf32(v.y), f2tf32(v.z), f2tf32(v.w));
            *(uint4*)&Bs[k][n4] = w;
        }
        __syncthreads();

#pragma unroll
        for (int ks = 0; ks < 4; ks++) {
            const int kb = ks * 8;
            uint32_t a[4][4], b[4][2];
#pragma unroll
            for (int mf = 0; mf < 4; mf++) {
                int m = wm * 64 + mf * 16 + g;
                a[mf][0] = As[m][kb + t];
                a[mf][1] = As[m + 8][kb + t];
                a[mf][2] = As[m][kb + t + 4];
                a[mf][3] = As[m + 8][kb + t + 4];
            }
#pragma unroll
            for (int nf = 0; nf < 4; nf++) {
                int n = wn * 32 + nf * 8 + g;
                b[nf][0] = Bs[kb + t][n];
                b[nf][1] = Bs[kb + t + 4][n];
            }
#pragma unroll
            for (int mf = 0; mf < 4; mf++)
#pragma unroll
                for (int nf = 0; nf < 4; nf++)
                    mma_tf32(acc[mf][nf], a[mf], b[nf]);
        }
        __syncthreads();
    }

    // Epilogue: +bias, float2 stores
#pragma unroll
    for (int mf = 0; mf < 4; mf++) {
        const int r0 = bm + wm * 64 + mf * 16 + g;
#pragma unroll
        for (int nf = 0; nf < 4; nf++) {
            const int c = bn + wn * 32 + nf * 8 + t * 2;
            float2 bv = *(const float2*)(bias + c);
            float2 o0 = { acc[mf][nf][0] + bv.x, acc[mf][nf][1] + bv.y };
            float2 o1 = { acc[mf][nf][2] + bv.x, acc[mf][nf][3] + bv.y };
            *(float2*)(C + (size_t)r0 * N + c) = o0;
            *(float2*)(C + (size_t)(r0 + 8) * N + c) = o1;
        }
    }
}

// ---------------------------------------------------------------------------
// TF32 flash attention. CTA: 64 queries x (head, batch). 4 warps; each warp
// owns one m16 row block (16 queries). Key tiles of 32. Online softmax in
// mma C-fragment registers; P round-trips smem within-warp only.
// ---------------------------------------------------------------------------
__global__ __launch_bounds__(128) void attn_tf32(const float* __restrict__ qkv,
                                                 float* __restrict__ out)
{
    __shared__ __align__(16) uint32_t Qs[64][68];  // [m][d]   stride 68 (=4 mod 32)
    __shared__ __align__(16) uint32_t Ks[32][68];  // [kk][d]  stride 68 (=4 mod 32)
    __shared__ __align__(16) uint32_t Vs[32][72];  // [kk][d]  stride 72 (=8 mod 32)
    __shared__ __align__(16) uint32_t Ps[64][36];  // [m][kk]  stride 36 (=4 mod 32)

    const int tid  = threadIdx.x;
    const int lane = tid & 31;
    const int warp = tid >> 5;
    const int g = lane >> 2;
    const int t = lane & 3;

    const int q0 = blockIdx.x * 64;
    const int h  = blockIdx.y;
    const int b  = blockIdx.z;

    const float* base = qkv + (size_t)b * SEQ * TRIPLE + h * DH;
    const float* Qg = base;
    const float* Kg = base + DATT;
    const float* Vg = base + 2 * DATT;

    // Load Q tile, pre-scaled by 1/sqrt(dh)=0.125, cvt tf32
#pragma unroll
    for (int i = 0; i < 8; i++) {
        int idx = tid + i * 128;
        int r = idx >> 4, d4 = (idx & 15) * 4;
        float4 v = *(const float4*)(Qg + (size_t)(q0 + r) * TRIPLE + d4);
        uint4 w = make_uint4(f2tf32(v.x * 0.125f), f2tf32(v.y * 0.125f),
                             f2tf32(v.z * 0.125f), f2tf32(v.w * 0.125f));
        *(uint4*)&Qs[r][d4] = w;
    }

    float m_lo = -1e30f, m_hi = -1e30f, l_lo = 0.0f, l_hi = 0.0f;
    float acc[8][4] = {};            // output: 8 n-frags over d=64
    const int mrow = warp * 16 + g;  // this thread's low row within CTA tile

    __syncthreads();

    for (int k0 = 0; k0 < SEQ; k0 += 32) {
        // Load K,V tiles (natural row-major, coalesced, cvt tf32)
#pragma unroll
        for (int i = 0; i < 4; i++) {
            int idx = tid + i * 128;
            int kk = idx >> 4, d4 = (idx & 15) * 4;
            float4 kv = *(const float4*)(Kg + (size_t)(k0 + kk) * TRIPLE + d4);
            *(uint4*)&Ks[kk][d4] = make_uint4(f2tf32(kv.x), f2tf32(kv.y),
                                              f2tf32(kv.z), f2tf32(kv.w));
            float4 vv = *(const float4*)(Vg + (size_t)(k0 + kk) * TRIPLE + d4);
            *(uint4*)&Vs[kk][d4] = make_uint4(f2tf32(vv.x), f2tf32(vv.y),
                                              f2tf32(vv.z), f2tf32(vv.w));
        }
        __syncthreads();

        // S = (Q*scale) @ K^T  : per-warp m16 x n32 x k64
        float s[4][4] = {};
#pragma unroll
        for (int ks = 0; ks < 8; ks++) {
            const int kb = ks * 8;
            uint32_t a[4];
            a[0] = Qs[mrow][kb + t];
            a[1] = Qs[mrow + 8][kb + t];
            a[2] = Qs[mrow][kb + t + 4];
            a[3] = Qs[mrow + 8][kb + t + 4];
#pragma unroll
            for (int nf = 0; nf < 4; nf++) {
                const int n = nf * 8 + g;          // key index for b-frag col
                uint32_t bb[2];
                bb[0] = Ks[n][kb + t];             // B[k=d][n=key] = Ks[key][d]
                bb[1] = Ks[n][kb + t + 4];
                mma_tf32(s[nf], a, bb);
            }
        }

        // Online softmax (two rows per thread: mrow / mrow+8)
        float mx_lo = -1e30f, mx_hi = -1e30f;
#pragma unroll
        for (int nf = 0; nf < 4; nf++) {
            mx_lo = fmaxf(mx_lo, fmaxf(s[nf][0], s[nf][1]));
            mx_hi = fmaxf(mx_hi, fmaxf(s[nf][2], s[nf][3]));
        }
        mx_lo = fmaxf(mx_lo, __shfl_xor_sync(0xffffffffu, mx_lo, 1));
        mx_lo = fmaxf(mx_lo, __shfl_xor_sync(0xffffffffu, mx_lo, 2));
        mx_hi = fmaxf(mx_hi, __shfl_xor_sync(0xffffffffu, mx_hi, 1));
        mx_hi = fmaxf(mx_hi, __shfl_xor_sync(0xffffffffu, mx_hi, 2));

        const float mn_lo = fmaxf(m_lo, mx_lo);
        const float mn_hi = fmaxf(m_hi, mx_hi);
        const float al_lo = __expf(m_lo - mn_lo);
        const float al_hi = __expf(m_hi - mn_hi);
        m_lo = mn_lo; m_hi = mn_hi;

        float sum_lo = 0.0f, sum_hi = 0.0f;
#pragma unroll
        for (int nf = 0; nf < 4; nf++) {
            s[nf][0] = __expf(s[nf][0] - mn_lo);
            s[nf][1] = __expf(s[nf][1] - mn_lo);
            s[nf][2] = __expf(s[nf][2] - mn_hi);
            s[nf][3] = __expf(s[nf][3] - mn_hi);
            sum_lo += s[nf][0] + s[nf][1];
            sum_hi += s[nf][2] + s[nf][3];
        }
        sum_lo += __shfl_xor_sync(0xffffffffu, sum_lo, 1);
        sum_lo += __shfl_xor_sync(0xffffffffu, sum_lo, 2);
        sum_hi += __shfl_xor_sync(0xffffffffu, sum_hi, 1);
        sum_hi += __shfl_xor_sync(0xffffffffu, sum_hi, 2);
        l_lo = l_lo * al_lo + sum_lo;
        l_hi = l_hi * al_hi + sum_hi;

#pragma unroll
        for (int nf = 0; nf < 8; nf++) {
            acc[nf][0] *= al_lo; acc[nf][1] *= al_lo;
            acc[nf][2] *= al_hi; acc[nf][3] *= al_hi;
        }

        // Store P (C-frag layout -> matrix layout), own rows only
#pragma unroll
        for (int nf = 0; nf < 4; nf++) {
            const int c = nf * 8 + t * 2;
            Ps[mrow][c]     = f2tf32(s[nf][0]);
            Ps[mrow][c + 1] = f2tf32(s[nf][1]);
            Ps[mrow + 8][c]     = f2tf32(s[nf][2]);
            Ps[mrow + 8][c + 1] = f2tf32(s[nf][3]);
        }
        __syncwarp();

        // acc += P @ V : m16 x n64 x k32
#pragma unroll
        for (int ks = 0; ks < 4; ks++) {
            const int kb = ks * 8;
            uint32_t a[4];
            a[0] = Ps[mrow][kb + t];
            a[1] = Ps[mrow + 8][kb + t];
            a[2] = Ps[mrow][kb + t + 4];
            a[3] = Ps[mrow + 8][kb + t + 4];
#pragma unroll
            for (int nf = 0; nf < 8; nf++) {
                const int n = nf * 8 + g;
                uint32_t bb[2];
                bb[0] = Vs[kb + t][n];
                bb[1] = Vs[kb + t + 4][n];
                mma_tf32(acc[nf], a, bb);
            }
        }
        __syncthreads();
    }

    // Write normalized output: (b, s, h*64 + d)
    const float il_lo = 1.0f / l_lo;
    const float il_hi = 1.0f / l_hi;
    const size_t row0 = (size_t)b * SEQ + q0 + mrow;
#pragma unroll
    for (int nf = 0; nf < 8; nf++) {
        const int c = h * DH + nf * 8 + t * 2;
        float2 o0 = { acc[nf][0] * il_lo, acc[nf][1] * il_lo };
        float2 o1 = { acc[nf][2] * il_hi, acc[nf][3] * il_hi };
        *(float2*)(out + row0 * DATT + c) = o0;
        *(float2*)(out + (row0 + 8) * DATT + c) = o1;
    }
}

// ---------------------------------------------------------------------------
extern "C" void kernel_launch(void* const* d_in, const int* in_sizes, int n_in,
                              void* d_out, int out_size)
{
    const float* x     = (const float*)d_in[0];
    const float* w_in  = (const float*)d_in[1];
    const float* b_in  = (const float*)d_in[2];
    const float* w_out = (const float*)d_in[3];
    const float* b_out = (const float*)d_in[4];
    float* out = (float*)d_out;

    float* qkv = nullptr;
    float* attn = nullptr;
    cudaGetSymbolAddress((void**)&qkv, g_qkv);
    cudaGetSymbolAddress((void**)&attn, g_attn);

    // 1) QKV = x @ w_in + b_in   (4096 x 3072 x 1024)
    dim3 g1(TRIPLE / 128, MROWS / 128);
    gemm_tf32_bias<<<g1, 256>>>(x, w_in, b_in, qkv, MROWS, TRIPLE, DE);

    // 2) attention
    dim3 g2(SEQ / 64, NH, BATCH);
    attn_tf32<<<g2, 128>>>(qkv, attn);

    // 3) out = attn @ w_out + b_out   (4096 x 1024 x 1024)
    dim3 g3(DATT / 128, MROWS / 128);
    gemm_tf32_bias<<<g3, 256>>>(attn, w_out, b_out, out, MROWS, DE, DATT);
}

// round 3
// speedup vs baseline: 3.4605x; 1.0363x over previous
#include <cuda_runtime.h>
#include <math.h>
#include <stdint.h>

#define BATCH 2
#define SEQ   2048
#define DE    1024
#define DATT  1024
#define NH    16
#define DH    64
#define TRIPLE (3*DATT)
#define MROWS (BATCH*SEQ)   /* 4096 */

// Scratch (device globals, allocation-free)
__device__ uint32_t g_xt[(size_t)MROWS * DE];            // x in tf32 bits
__device__ uint32_t g_wint[(size_t)DE * TRIPLE];         // w_in tf32
__device__ uint32_t g_woutt[(size_t)DATT * DE];          // w_out tf32
__device__ uint32_t g_qkv[(size_t)3 * BATCH * NH * SEQ * DH];  // (which,b,h,s,d) tf32
__device__ uint32_t g_attn[(size_t)MROWS * DATT];        // (b*s, h*64+d) tf32

__device__ __forceinline__ uint32_t f2tf32(float f) {
    uint32_t u;
    asm("cvt.rna.tf32.f32 %0, %1;" : "=r"(u) : "f"(f));
    return u;
}
__device__ __forceinline__ float ex2f(float x) {
    float y;
    asm("ex2.approx.f32 %0, %1;" : "=f"(y) : "f"(x));
    return y;
}
__device__ __forceinline__ void mma_tf32(float* d, const uint32_t* a, const uint32_t* b) {
    asm volatile(
        "mma.sync.aligned.m16n8k8.row.col.f32.tf32.tf32.f32 "
        "{%0,%1,%2,%3}, {%4,%5,%6,%7}, {%8,%9}, {%0,%1,%2,%3};\n"
        : "+f"(d[0]), "+f"(d[1]), "+f"(d[2]), "+f"(d[3])
        : "r"(a[0]), "r"(a[1]), "r"(a[2]), "r"(a[3]), "r"(b[0]), "r"(b[1]));
}
__device__ __forceinline__ void cp16(const uint32_t* s, const uint32_t* g) {
    uint32_t sa = (uint32_t)__cvta_generic_to_shared(s);
    asm volatile("cp.async.cg.shared.global [%0], [%1], 16;"
                 :: "r"(sa), "l"((unsigned long long)__cvta_generic_to_global(g)));
}
#define CP_COMMIT asm volatile("cp.async.commit_group;")
#define CP_WAIT(n) asm volatile("cp.async.wait_group %0;" :: "n"(n))

// ---------------------------------------------------------------------------
// Elementwise fp32 -> tf32 bits
// ---------------------------------------------------------------------------
__global__ void cvt_tf32(const float4* __restrict__ in, uint4* __restrict__ out) {
    int i = blockIdx.x * blockDim.x + threadIdx.x;
    float4 v = in[i];
    out[i] = make_uint4(f2tf32(v.x), f2tf32(v.y), f2tf32(v.z), f2tf32(v.w));
}

// ---------------------------------------------------------------------------
// TF32 GEMM + bias, cp.async 3-stage pipeline.
// C[M,N] = A[M,K] @ B[K,N] + bias.  A,B pre-converted tf32 (u32 bits).
// mode 0: fp32 row-major out.  mode 1: tf32 bits into (which,b,h,s,d) qkv.
// ---------------------------------------------------------------------------
#define ASZ (128*36)
#define BSZ (32*136)
#define GEMM_SMEM (3*(ASZ+BSZ)*4)

__global__ __launch_bounds__(256) void gemm_tf32_pipe(
    const uint32_t* __restrict__ A, const uint32_t* __restrict__ B,
    const float* __restrict__ bias, void* __restrict__ Cv,
    int M, int N, int K, int mode)
{
    extern __shared__ uint32_t sm[];
    uint32_t* sA = sm;                 // 3 stages of [128][36]
    uint32_t* sB = sm + 3 * ASZ;       // 3 stages of [32][136]

    const int tid  = threadIdx.x;
    const int lane = tid & 31;
    const int warp = tid >> 5;
    const int wm = warp >> 2, wn = warp & 3;
    const int g  = lane >> 2, t = lane & 3;
    const int bm = blockIdx.y * 128;
    const int bn = blockIdx.x * 128;
    const int nk = K >> 5;

    // per-thread copy coordinates
    const int am = tid >> 3, ac4 = (tid & 7) * 4;        // A: 2 rows per thread pass
    const int bk = tid >> 5, bn4 = (tid & 31) * 4;

#define ISSUE_TILE(ki, st) do {                                               \
        const uint32_t* Ag = A + (size_t)(bm) * K + ((ki) << 5);              \
        const uint32_t* Bg = B + (size_t)((ki) << 5) * N + bn;                \
        uint32_t* sa = sA + (st) * ASZ;                                       \
        uint32_t* sb = sB + (st) * BSZ;                                       \
        _Pragma("unroll")                                                     \
        for (int i = 0; i < 4; i++) {                                         \
            int m = am + i * 32;                                              \
            cp16(sa + m * 36 + ac4, Ag + (size_t)m * K + ac4);                \
        }                                                                     \
        _Pragma("unroll")                                                     \
        for (int i = 0; i < 4; i++) {                                         \
            int k = bk + i * 8;                                               \
            cp16(sb + k * 136 + bn4, Bg + (size_t)k * N + bn4);               \
        }                                                                     \
        CP_COMMIT;                                                            \
    } while (0)

    float acc[4][4][4] = {};

    ISSUE_TILE(0, 0);
    if (nk > 1) ISSUE_TILE(1, 1);

#pragma unroll 1
    for (int i = 0; i < nk; i++) {
        if (i + 2 < nk) { ISSUE_TILE(i + 2, (i + 2) % 3); CP_WAIT(2); }
        else if (i + 1 < nk) { CP_WAIT(1); }
        else { CP_WAIT(0); }
        __syncthreads();

        const uint32_t* As = sA + (i % 3) * ASZ;
        const uint32_t* Bs = sB + (i % 3) * BSZ;
#pragma unroll
        for (int ks = 0; ks < 4; ks++) {
            const int kb = ks * 8;
            uint32_t a[4][4], b[4][2];
#pragma unroll
            for (int mf = 0; mf < 4; mf++) {
                int m = wm * 64 + mf * 16 + g;
                a[mf][0] = As[m * 36 + kb + t];
                a[mf][1] = As[(m + 8) * 36 + kb + t];
                a[mf][2] = As[m * 36 + kb + t + 4];
                a[mf][3] = As[(m + 8) * 36 + kb + t + 4];
            }
#pragma unroll
            for (int nf = 0; nf < 4; nf++) {
                int n = wn * 32 + nf * 8 + g;
                b[nf][0] = Bs[(kb + t) * 136 + n];
                b[nf][1] = Bs[(kb + t + 4) * 136 + n];
            }
#pragma unroll
            for (int mf = 0; mf < 4; mf++)
#pragma unroll
                for (int nf = 0; nf < 4; nf++)
                    mma_tf32(acc[mf][nf], a[mf], b[nf]);
        }
        __syncthreads();
    }

    if (mode == 0) {
        float* C = (float*)Cv;
#pragma unroll
        for (int mf = 0; mf < 4; mf++) {
            const int r0 = bm + wm * 64 + mf * 16 + g;
#pragma unroll
            for (int nf = 0; nf < 4; nf++) {
                const int c = bn + wn * 32 + nf * 8 + t * 2;
                float2 bv = *(const float2*)(bias + c);
                float2 o0 = { acc[mf][nf][0] + bv.x, acc[mf][nf][1] + bv.y };
                float2 o1 = { acc[mf][nf][2] + bv.x, acc[mf][nf][3] + bv.y };
                *(float2*)(C + (size_t)r0 * N + c) = o0;
                *(float2*)(C + (size_t)(r0 + 8) * N + c) = o1;
            }
        }
    } else {
        uint32_t* C = (uint32_t*)Cv;
#pragma unroll
        for (int mf = 0; mf < 4; mf++) {
            const int r0 = bm + wm * 64 + mf * 16 + g;
#pragma unroll
            for (int nf = 0; nf < 4; nf++) {
                const int c = bn + wn * 32 + nf * 8 + t * 2;
                float2 bv = *(const float2*)(bias + c);
                const int which = c >> 10, rem = c & 1023;
                const int h = rem >> 6, d = rem & 63;
#pragma unroll
                for (int rr = 0; rr < 2; rr++) {
                    const int r = r0 + rr * 8;
                    const int b_ = r >> 11, s_ = r & 2047;
                    size_t base = ((((size_t)which * BATCH + b_) * NH + h) << 17)
                                + ((size_t)s_ << 6) + d;
                    uint2 o = { f2tf32(acc[mf][nf][rr * 2]     + bv.x),
                                f2tf32(acc[mf][nf][rr * 2 + 1] + bv.y) };
                    *(uint2*)(C + base) = o;
                }
            }
        }
    }
#undef ISSUE_TILE
}

// ---------------------------------------------------------------------------
// TF32 flash attention. CTA: 128 queries x (head, batch), 8 warps, each warp
// one m16 block. Key tiles of 32, cp.async double-buffered. Online softmax
// via ex2 with folded 1/sqrt(dh) scale. Writes tf32 bits to g_attn.
// ---------------------------------------------------------------------------
#define QSZ (128*68)
#define KSZ (32*68)
#define VSZ (32*72)
#define PSZ (128*36)
#define ATT_SMEM ((QSZ + 2*KSZ + 2*VSZ + PSZ)*4)

__global__ __launch_bounds__(256) void attn_tf32_pipe(
    const uint32_t* __restrict__ qkv, uint32_t* __restrict__ out)
{
    extern __shared__ uint32_t sm[];
    uint32_t* Qs = sm;                       // [128][68]
    uint32_t* Ks = sm + QSZ;                 // [2][32][68]
    uint32_t* Vs = Ks + 2 * KSZ;             // [2][32][72]
    uint32_t* Ps = Vs + 2 * VSZ;             // [128][36]

    const int tid  = threadIdx.x;
    const int lane = tid & 31;
    const int warp = tid >> 5;
    const int g = lane >> 2, t = lane & 3;

    const int q0 = blockIdx.x * 128;
    const int h  = blockIdx.y;
    const int b  = blockIdx.z;

    const size_t plane = (size_t)SEQ * DH;   // 1<<17
    const uint32_t* Qg = qkv + ((size_t)(0 * BATCH + b) * NH + h) * plane;
    const uint32_t* Kg = qkv + ((size_t)(1 * BATCH + b) * NH + h) * plane;
    const uint32_t* Vg = qkv + ((size_t)(2 * BATCH + b) * NH + h) * plane;

    const int half = tid >> 7;               // 0: K copier, 1: V copier
    const int tt   = tid & 127;

#define ISSUE_KV(kt, buf) do {                                                \
        const int k0_ = (kt) << 5;                                            \
        uint32_t* kb_ = Ks + (buf) * KSZ;                                     \
        uint32_t* vb_ = Vs + (buf) * VSZ;                                     \
        _Pragma("unroll")                                                     \
        for (int j = 0; j < 4; j++) {                                         \
            int chunk = tt + j * 128;                                         \
            int r = chunk >> 4, c4 = (chunk & 15) * 4;                        \
            if (half == 0) cp16(kb_ + r * 68 + c4, Kg + (size_t)(k0_ + r) * DH + c4); \
            else           cp16(vb_ + r * 72 + c4, Vg + (size_t)(k0_ + r) * DH + c4); \
        }                                                                     \
        CP_COMMIT;                                                            \
    } while (0)

    ISSUE_KV(0, 0);

    // Q tile (plain vector loads, overlapped with first KV cp.async)
#pragma unroll
    for (int i = 0; i < 8; i++) {
        int idx = tid + i * 256;
        int r = idx >> 4, c4 = (idx & 15) * 4;
        uint4 v = *(const uint4*)(Qg + (size_t)(q0 + r) * DH + c4);
        *(uint4*)&Qs[r * 68 + c4] = v;
    }

    float m_lo = -1e30f, m_hi = -1e30f, l_lo = 0.0f, l_hi = 0.0f;
    float acc[8][4] = {};
    const int mrow = warp * 16 + g;
    const float C2 = 0.18033688011112042f;   // 0.125 * log2(e)

    const int NKT = SEQ / 32;
#pragma unroll 1
    for (int kt = 0; kt < NKT; kt++) {
        if (kt + 1 < NKT) { ISSUE_KV(kt + 1, (kt + 1) & 1); CP_WAIT(1); }
        else              { CP_WAIT(0); }
        __syncthreads();

        const uint32_t* Kb = Ks + (kt & 1) * KSZ;
        const uint32_t* Vb = Vs + (kt & 1) * VSZ;

        // S = Q @ K^T : m16 x n32 x k64
        float s[4][4] = {};
#pragma unroll
        for (int ks = 0; ks < 8; ks++) {
            const int kb = ks * 8;
            uint32_t a[4];
            a[0] = Qs[mrow * 68 + kb + t];
            a[1] = Qs[(mrow + 8) * 68 + kb + t];
            a[2] = Qs[mrow * 68 + kb + t + 4];
            a[3] = Qs[(mrow + 8) * 68 + kb + t + 4];
#pragma unroll
            for (int nf = 0; nf < 4; nf++) {
                const int n = nf * 8 + g;
                uint32_t bb[2] = { Kb[n * 68 + kb + t], Kb[n * 68 + kb + t + 4] };
                mma_tf32(s[nf], a, bb);
            }
        }

        // Online softmax (rows mrow / mrow+8), scale folded into ex2
        float mx_lo = -1e30f, mx_hi = -1e30f;
#pragma unroll
        for (int nf = 0; nf < 4; nf++) {
            mx_lo = fmaxf(mx_lo, fmaxf(s[nf][0], s[nf][1]));
            mx_hi = fmaxf(mx_hi, fmaxf(s[nf][2], s[nf][3]));
        }
        mx_lo = fmaxf(mx_lo, __shfl_xor_sync(0xffffffffu, mx_lo, 1));
        mx_lo = fmaxf(mx_lo, __shfl_xor_sync(0xffffffffu, mx_lo, 2));
        mx_hi = fmaxf(mx_hi, __shfl_xor_sync(0xffffffffu, mx_hi, 1));
        mx_hi = fmaxf(mx_hi, __shfl_xor_sync(0xffffffffu, mx_hi, 2));

        const float mn_lo = fmaxf(m_lo, mx_lo);
        const float mn_hi = fmaxf(m_hi, mx_hi);
        const float al_lo = ex2f((m_lo - mn_lo) * C2);
        const float al_hi = ex2f((m_hi - mn_hi) * C2);
        m_lo = mn_lo; m_hi = mn_hi;

        float sum_lo = 0.0f, sum_hi = 0.0f;
#pragma unroll
        for (int nf = 0; nf < 4; nf++) {
            s[nf][0] = ex2f((s[nf][0] - mn_lo) * C2);
            s[nf][1] = ex2f((s[nf][1] - mn_lo) * C2);
            s[nf][2] = ex2f((s[nf][2] - mn_hi) * C2);
            s[nf][3] = ex2f((s[nf][3] - mn_hi) * C2);
            sum_lo += s[nf][0] + s[nf][1];
            sum_hi += s[nf][2] + s[nf][3];
        }
        sum_lo += __shfl_xor_sync(0xffffffffu, sum_lo, 1);
        sum_lo += __shfl_xor_sync(0xffffffffu, sum_lo, 2);
        sum_hi += __shfl_xor_sync(0xffffffffu, sum_hi, 1);
        sum_hi += __shfl_xor_sync(0xffffffffu, sum_hi, 2);
        l_lo = l_lo * al_lo + sum_lo;
        l_hi = l_hi * al_hi + sum_hi;

#pragma unroll
        for (int nf = 0; nf < 8; nf++) {
            acc[nf][0] *= al_lo; acc[nf][1] *= al_lo;
            acc[nf][2] *= al_hi; acc[nf][3] *= al_hi;
        }

        // P -> smem (own rows only)
#pragma unroll
        for (int nf = 0; nf < 4; nf++) {
            const int c = nf * 8 + t * 2;
            Ps[mrow * 36 + c]           = f2tf32(s[nf][0]);
            Ps[mrow * 36 + c + 1]       = f2tf32(s[nf][1]);
            Ps[(mrow + 8) * 36 + c]     = f2tf32(s[nf][2]);
            Ps[(mrow + 8) * 36 + c + 1] = f2tf32(s[nf][3]);
        }
        __syncwarp();

        // acc += P @ V : m16 x n64 x k32
#pragma unroll
        for (int ks = 0; ks < 4; ks++) {
            const int kb = ks * 8;
            uint32_t a[4];
            a[0] = Ps[mrow * 36 + kb + t];
            a[1] = Ps[(mrow + 8) * 36 + kb + t];
            a[2] = Ps[mrow * 36 + kb + t + 4];
            a[3] = Ps[(mrow + 8) * 36 + kb + t + 4];
#pragma unroll
            for (int nf = 0; nf < 8; nf++) {
                const int n = nf * 8 + g;
                uint32_t bb[2] = { Vb[(kb + t) * 72 + n], Vb[(kb + t + 4) * 72 + n] };
                mma_tf32(acc[nf], a, bb);
            }
        }
        __syncthreads();
    }

    // Write tf32 bits: row = b*SEQ + q, col = h*64 + d
    const float il_lo = 1.0f / l_lo;
    const float il_hi = 1.0f / l_hi;
    const size_t row0 = (size_t)b * SEQ + q0 + mrow;
#pragma unroll
    for (int nf = 0; nf < 8; nf++) {
        const int c = h * DH + nf * 8 + t * 2;
        uint2 o0 = { f2tf32(acc[nf][0] * il_lo), f2tf32(acc[nf][1] * il_lo) };
        uint2 o1 = { f2tf32(acc[nf][2] * il_hi), f2tf32(acc[nf][3] * il_hi) };
        *(uint2*)(out + row0 * DATT + c) = o0;
        *(uint2*)(out + (row0 + 8) * DATT + c) = o1;
    }
#undef ISSUE_KV
}

// ---------------------------------------------------------------------------
extern "C" void kernel_launch(void* const* d_in, const int* in_sizes, int n_in,
                              void* d_out, int out_size)
{
    const float* x     = (const float*)d_in[0];
    const float* w_in  = (const float*)d_in[1];
    const float* b_in  = (const float*)d_in[2];
    const float* w_out = (const float*)d_in[3];
    const float* b_out = (const float*)d_in[4];
    float* out = (float*)d_out;

    uint32_t *xt, *wint, *woutt, *qkv, *attn;
    cudaGetSymbolAddress((void**)&xt,    g_xt);
    cudaGetSymbolAddress((void**)&wint,  g_wint);
    cudaGetSymbolAddress((void**)&woutt, g_woutt);
    cudaGetSymbolAddress((void**)&qkv,   g_qkv);
    cudaGetSymbolAddress((void**)&attn,  g_attn);

    cudaFuncSetAttribute(gemm_tf32_pipe, cudaFuncAttributeMaxDynamicSharedMemorySize, GEMM_SMEM);
    cudaFuncSetAttribute(attn_tf32_pipe, cudaFuncAttributeMaxDynamicSharedMemorySize, ATT_SMEM);

    // 0) pre-convert inputs to tf32
    cvt_tf32<<<(MROWS * DE / 4) / 256, 256>>>((const float4*)x, (uint4*)xt);
    cvt_tf32<<<(DE * TRIPLE / 4) / 256, 256>>>((const float4*)w_in, (uint4*)wint);
    cvt_tf32<<<(DATT * DE / 4) / 256, 256>>>((const float4*)w_out, (uint4*)woutt);

    // 1) QKV = x @ w_in + b_in  -> tf32 qkv in (which,b,h,s,d)
    dim3 g1(TRIPLE / 128, MROWS / 128);
    gemm_tf32_pipe<<<g1, 256, GEMM_SMEM>>>(xt, wint, b_in, qkv, MROWS, TRIPLE, DE, 1);

    // 2) attention -> tf32 attn
    dim3 g2(SEQ / 128, NH, BATCH);
    attn_tf32_pipe<<<g2, 256, ATT_SMEM>>>(qkv, attn);

    // 3) out = attn @ w_out + b_out (fp32)
    dim3 g3(DE / 128, MROWS / 128);
    gemm_tf32_pipe<<<g3, 256, GEMM_SMEM>>>(attn, woutt, b_out, out, MROWS, DE, DATT, 0);
}

// round 4
// speedup vs baseline: 3.4627x; 1.0006x over previous
#include <cuda_runtime.h>
#include <math.h>
#include <stdint.h>

#define BATCH 2
#define SEQ   2048
#define DE    1024
#define DATT  1024
#define NH    16
#define DH    64
#define TRIPLE (3*DATT)
#define MROWS (BATCH*SEQ)   /* 4096 */

// Scratch (device globals, allocation-free)
__device__ uint32_t g_xt[(size_t)MROWS * DE];            // x in tf32 bits
__device__ uint32_t g_wint[(size_t)DE * TRIPLE];         // w_in tf32
__device__ uint32_t g_woutt[(size_t)DATT * DE];          // w_out tf32
__device__ uint32_t g_qkv[(size_t)3 * BATCH * NH * SEQ * DH];  // (which,b,h,s,d) tf32
__device__ uint32_t g_attn[(size_t)MROWS * DATT];        // (b*s, h*64+d) tf32

__device__ __forceinline__ uint32_t f2tf32(float f) {
    uint32_t u;
    asm("cvt.rna.tf32.f32 %0, %1;" : "=r"(u) : "f"(f));
    return u;
}
__device__ __forceinline__ float ex2f(float x) {
    float y;
    asm("ex2.approx.f32 %0, %1;" : "=f"(y) : "f"(x));
    return y;
}
__device__ __forceinline__ void mma_tf32(float* d, const uint32_t* a, const uint32_t* b) {
    asm volatile(
        "mma.sync.aligned.m16n8k8.row.col.f32.tf32.tf32.f32 "
        "{%0,%1,%2,%3}, {%4,%5,%6,%7}, {%8,%9}, {%0,%1,%2,%3};\n"
        : "+f"(d[0]), "+f"(d[1]), "+f"(d[2]), "+f"(d[3])
        : "r"(a[0]), "r"(a[1]), "r"(a[2]), "r"(a[3]), "r"(b[0]), "r"(b[1]));
}
__device__ __forceinline__ void cp16(const uint32_t* s, const uint32_t* g) {
    uint32_t sa = (uint32_t)__cvta_generic_to_shared(s);
    asm volatile("cp.async.cg.shared.global [%0], [%1], 16;"
                 :: "r"(sa), "l"((unsigned long long)__cvta_generic_to_global(g)));
}
#define CP_COMMIT asm volatile("cp.async.commit_group;")
#define CP_WAIT(n) asm volatile("cp.async.wait_group %0;" :: "n"(n))

// ---------------------------------------------------------------------------
// Elementwise fp32 -> tf32 bits
// ---------------------------------------------------------------------------
__global__ void cvt_tf32(const float4* __restrict__ in, uint4* __restrict__ out) {
    int i = blockIdx.x * blockDim.x + threadIdx.x;
    float4 v = in[i];
    out[i] = make_uint4(f2tf32(v.x), f2tf32(v.y), f2tf32(v.z), f2tf32(v.w));
}

// ---------------------------------------------------------------------------
// TF32 GEMM + bias, cp.async 3-stage pipeline.
// C[M,N] = A[M,K] @ B[K,N] + bias.  A,B pre-converted tf32 (u32 bits).
// mode 0: fp32 row-major out.  mode 1: tf32 bits into (which,b,h,s,d) qkv.
// ---------------------------------------------------------------------------
#define ASZ (128*36)
#define BSZ (32*136)
#define GEMM_SMEM (3*(ASZ+BSZ)*4)

__global__ __launch_bounds__(256) void gemm_tf32_pipe(
    const uint32_t* __restrict__ A, const uint32_t* __restrict__ B,
    const float* __restrict__ bias, void* __restrict__ Cv,
    int M, int N, int K, int mode)
{
    extern __shared__ uint32_t sm[];
    uint32_t* sA = sm;                 // 3 stages of [128][36]
    uint32_t* sB = sm + 3 * ASZ;       // 3 stages of [32][136]

    const int tid  = threadIdx.x;
    const int lane = tid & 31;
    const int warp = tid >> 5;
    const int wm = warp >> 2, wn = warp & 3;
    const int g  = lane >> 2, t = lane & 3;
    const int bm = blockIdx.y * 128;
    const int bn = blockIdx.x * 128;
    const int nk = K >> 5;

    // per-thread copy coordinates
    const int am = tid >> 3, ac4 = (tid & 7) * 4;        // A: 2 rows per thread pass
    const int bk = tid >> 5, bn4 = (tid & 31) * 4;

#define ISSUE_TILE(ki, st) do {                                               \
        const uint32_t* Ag = A + (size_t)(bm) * K + ((ki) << 5);              \
        const uint32_t* Bg = B + (size_t)((ki) << 5) * N + bn;                \
        uint32_t* sa = sA + (st) * ASZ;                                       \
        uint32_t* sb = sB + (st) * BSZ;                                       \
        _Pragma("unroll")                                                     \
        for (int i = 0; i < 4; i++) {                                         \
            int m = am + i * 32;                                              \
            cp16(sa + m * 36 + ac4, Ag + (size_t)m * K + ac4);                \
        }                                                                     \
        _Pragma("unroll")                                                     \
        for (int i = 0; i < 4; i++) {                                         \
            int k = bk + i * 8;                                               \
            cp16(sb + k * 136 + bn4, Bg + (size_t)k * N + bn4);               \
        }                                                                     \
        CP_COMMIT;                                                            \
    } while (0)

    float acc[4][4][4] = {};

    ISSUE_TILE(0, 0);
    if (nk > 1) ISSUE_TILE(1, 1);

#pragma unroll 1
    for (int i = 0; i < nk; i++) {
        if (i + 2 < nk) { ISSUE_TILE(i + 2, (i + 2) % 3); CP_WAIT(2); }
        else if (i + 1 < nk) { CP_WAIT(1); }
        else { CP_WAIT(0); }
        __syncthreads();

        const uint32_t* As = sA + (i % 3) * ASZ;
        const uint32_t* Bs = sB + (i % 3) * BSZ;
#pragma unroll
        for (int ks = 0; ks < 4; ks++) {
            const int kb = ks * 8;
            uint32_t a[4][4], b[4][2];
#pragma unroll
            for (int mf = 0; mf < 4; mf++) {
                int m = wm * 64 + mf * 16 + g;
                a[mf][0] = As[m * 36 + kb + t];
                a[mf][1] = As[(m + 8) * 36 + kb + t];
                a[mf][2] = As[m * 36 + kb + t + 4];
                a[mf][3] = As[(m + 8) * 36 + kb + t + 4];
            }
#pragma unroll
            for (int nf = 0; nf < 4; nf++) {
                int n = wn * 32 + nf * 8 + g;
                b[nf][0] = Bs[(kb + t) * 136 + n];
                b[nf][1] = Bs[(kb + t + 4) * 136 + n];
            }
#pragma unroll
            for (int mf = 0; mf < 4; mf++)
#pragma unroll
                for (int nf = 0; nf < 4; nf++)
                    mma_tf32(acc[mf][nf], a[mf], b[nf]);
        }
        __syncthreads();
    }

    if (mode == 0) {
        float* C = (float*)Cv;
#pragma unroll
        for (int mf = 0; mf < 4; mf++) {
            const int r0 = bm + wm * 64 + mf * 16 + g;
#pragma unroll
            for (int nf = 0; nf < 4; nf++) {
                const int c = bn + wn * 32 + nf * 8 + t * 2;
                float2 bv = *(const float2*)(bias + c);
                float2 o0 = { acc[mf][nf][0] + bv.x, acc[mf][nf][1] + bv.y };
                float2 o1 = { acc[mf][nf][2] + bv.x, acc[mf][nf][3] + bv.y };
                *(float2*)(C + (size_t)r0 * N + c) = o0;
                *(float2*)(C + (size_t)(r0 + 8) * N + c) = o1;
            }
        }
    } else {
        uint32_t* C = (uint32_t*)Cv;
#pragma unroll
        for (int mf = 0; mf < 4; mf++) {
            const int r0 = bm + wm * 64 + mf * 16 + g;
#pragma unroll
            for (int nf = 0; nf < 4; nf++) {
                const int c = bn + wn * 32 + nf * 8 + t * 2;
                float2 bv = *(const float2*)(bias + c);
                const int which = c >> 10, rem = c & 1023;
                const int h = rem >> 6, d = rem & 63;
#pragma unroll
                for (int rr = 0; rr < 2; rr++) {
                    const int r = r0 + rr * 8;
                    const int b_ = r >> 11, s_ = r & 2047;
                    size_t base = ((((size_t)which * BATCH + b_) * NH + h) << 17)
                                + ((size_t)s_ << 6) + d;
                    uint2 o = { f2tf32(acc[mf][nf][rr * 2]     + bv.x),
                                f2tf32(acc[mf][nf][rr * 2 + 1] + bv.y) };
                    *(uint2*)(C + base) = o;
                }
            }
        }
    }
#undef ISSUE_TILE
}

// ---------------------------------------------------------------------------
// TF32 flash attention. CTA: 128 queries x (head, batch), 8 warps, each warp
// one m16 block. Key tiles of 32, cp.async double-buffered. Online softmax
// via ex2 with folded 1/sqrt(dh) scale. Writes tf32 bits to g_attn.
// ---------------------------------------------------------------------------
#define QSZ (128*68)
#define KSZ (32*68)
#define VSZ (32*72)
#define PSZ (128*36)
#define ATT_SMEM ((QSZ + 2*KSZ + 2*VSZ + PSZ)*4)

__global__ __launch_bounds__(256) void attn_tf32_pipe(
    const uint32_t* __restrict__ qkv, uint32_t* __restrict__ out)
{
    extern __shared__ uint32_t sm[];
    uint32_t* Qs = sm;                       // [128][68]
    uint32_t* Ks = sm + QSZ;                 // [2][32][68]
    uint32_t* Vs = Ks + 2 * KSZ;             // [2][32][72]
    uint32_t* Ps = Vs + 2 * VSZ;             // [128][36]

    const int tid  = threadIdx.x;
    const int lane = tid & 31;
    const int warp = tid >> 5;
    const int g = lane >> 2, t = lane & 3;

    const int q0 = blockIdx.x * 128;
    const int h  = blockIdx.y;
    const int b  = blockIdx.z;

    const size_t plane = (size_t)SEQ * DH;   // 1<<17
    const uint32_t* Qg = qkv + ((size_t)(0 * BATCH + b) * NH + h) * plane;
    const uint32_t* Kg = qkv + ((size_t)(1 * BATCH + b) * NH + h) * plane;
    const uint32_t* Vg = qkv + ((size_t)(2 * BATCH + b) * NH + h) * plane;

    const int half = tid >> 7;               // 0: K copier, 1: V copier
    const int tt   = tid & 127;

#define ISSUE_KV(kt, buf) do {                                                \
        const int k0_ = (kt) << 5;                                            \
        uint32_t* kb_ = Ks + (buf) * KSZ;                                     \
        uint32_t* vb_ = Vs + (buf) * VSZ;                                     \
        _Pragma("unroll")                                                     \
        for (int j = 0; j < 4; j++) {                                         \
            int chunk = tt + j * 128;                                         \
            int r = chunk >> 4, c4 = (chunk & 15) * 4;                        \
            if (half == 0) cp16(kb_ + r * 68 + c4, Kg + (size_t)(k0_ + r) * DH + c4); \
            else           cp16(vb_ + r * 72 + c4, Vg + (size_t)(k0_ + r) * DH + c4); \
        }                                                                     \
        CP_COMMIT;                                                            \
    } while (0)

    ISSUE_KV(0, 0);

    // Q tile (plain vector loads, overlapped with first KV cp.async)
#pragma unroll
    for (int i = 0; i < 8; i++) {
        int idx = tid + i * 256;
        int r = idx >> 4, c4 = (idx & 15) * 4;
        uint4 v = *(const uint4*)(Qg + (size_t)(q0 + r) * DH + c4);
        *(uint4*)&Qs[r * 68 + c4] = v;
    }

    float m_lo = -1e30f, m_hi = -1e30f, l_lo = 0.0f, l_hi = 0.0f;
    float acc[8][4] = {};
    const int mrow = warp * 16 + g;
    const float C2 = 0.18033688011112042f;   // 0.125 * log2(e)

    const int NKT = SEQ / 32;
#pragma unroll 1
    for (int kt = 0; kt < NKT; kt++) {
        if (kt + 1 < NKT) { ISSUE_KV(kt + 1, (kt + 1) & 1); CP_WAIT(1); }
        else              { CP_WAIT(0); }
        __syncthreads();

        const uint32_t* Kb = Ks + (kt & 1) * KSZ;
        const uint32_t* Vb = Vs + (kt & 1) * VSZ;

        // S = Q @ K^T : m16 x n32 x k64
        float s[4][4] = {};
#pragma unroll
        for (int ks = 0; ks < 8; ks++) {
            const int kb = ks * 8;
            uint32_t a[4];
            a[0] = Qs[mrow * 68 + kb + t];
            a[1] = Qs[(mrow + 8) * 68 + kb + t];
            a[2] = Qs[mrow * 68 + kb + t + 4];
            a[3] = Qs[(mrow + 8) * 68 + kb + t + 4];
#pragma unroll
            for (int nf = 0; nf < 4; nf++) {
                const int n = nf * 8 + g;
                uint32_t bb[2] = { Kb[n * 68 + kb + t], Kb[n * 68 + kb + t + 4] };
                mma_tf32(s[nf], a, bb);
            }
        }

        // Online softmax (rows mrow / mrow+8), scale folded into ex2
        float mx_lo = -1e30f, mx_hi = -1e30f;
#pragma unroll
        for (int nf = 0; nf < 4; nf++) {
            mx_lo = fmaxf(mx_lo, fmaxf(s[nf][0], s[nf][1]));
            mx_hi = fmaxf(mx_hi, fmaxf(s[nf][2], s[nf][3]));
        }
        mx_lo = fmaxf(mx_lo, __shfl_xor_sync(0xffffffffu, mx_lo, 1));
        mx_lo = fmaxf(mx_lo, __shfl_xor_sync(0xffffffffu, mx_lo, 2));
        mx_hi = fmaxf(mx_hi, __shfl_xor_sync(0xffffffffu, mx_hi, 1));
        mx_hi = fmaxf(mx_hi, __shfl_xor_sync(0xffffffffu, mx_hi, 2));

        const float mn_lo = fmaxf(m_lo, mx_lo);
        const float mn_hi = fmaxf(m_hi, mx_hi);
        const float al_lo = ex2f((m_lo - mn_lo) * C2);
        const float al_hi = ex2f((m_hi - mn_hi) * C2);
        m_lo = mn_lo; m_hi = mn_hi;

        float sum_lo = 0.0f, sum_hi = 0.0f;
#pragma unroll
        for (int nf = 0; nf < 4; nf++) {
            s[nf][0] = ex2f((s[nf][0] - mn_lo) * C2);
            s[nf][1] = ex2f((s[nf][1] - mn_lo) * C2);
            s[nf][2] = ex2f((s[nf][2] - mn_hi) * C2);
            s[nf][3] = ex2f((s[nf][3] - mn_hi) * C2);
            sum_lo += s[nf][0] + s[nf][1];
            sum_hi += s[nf][2] + s[nf][3];
        }
        sum_lo += __shfl_xor_sync(0xffffffffu, sum_lo, 1);
        sum_lo += __shfl_xor_sync(0xffffffffu, sum_lo, 2);
        sum_hi += __shfl_xor_sync(0xffffffffu, sum_hi, 1);
        sum_hi += __shfl_xor_sync(0xffffffffu, sum_hi, 2);
        l_lo = l_lo * al_lo + sum_lo;
        l_hi = l_hi * al_hi + sum_hi;

#pragma unroll
        for (int nf = 0; nf < 8; nf++) {
            acc[nf][0] *= al_lo; acc[nf][1] *= al_lo;
            acc[nf][2] *= al_hi; acc[nf][3] *= al_hi;
        }

        // P -> smem (own rows only)
#pragma unroll
        for (int nf = 0; nf < 4; nf++) {
            const int c = nf * 8 + t * 2;
            Ps[mrow * 36 + c]           = f2tf32(s[nf][0]);
            Ps[mrow * 36 + c + 1]       = f2tf32(s[nf][1]);
            Ps[(mrow + 8) * 36 + c]     = f2tf32(s[nf][2]);
            Ps[(mrow + 8) * 36 + c + 1] = f2tf32(s[nf][3]);
        }
        __syncwarp();

        // acc += P @ V : m16 x n64 x k32
#pragma unroll
        for (int ks = 0; ks < 4; ks++) {
            const int kb = ks * 8;
            uint32_t a[4];
            a[0] = Ps[mrow * 36 + kb + t];
            a[1] = Ps[(mrow + 8) * 36 + kb + t];
            a[2] = Ps[mrow * 36 + kb + t + 4];
            a[3] = Ps[(mrow + 8) * 36 + kb + t + 4];
#pragma unroll
            for (int nf = 0; nf < 8; nf++) {
                const int n = nf * 8 + g;
                uint32_t bb[2] = { Vb[(kb + t) * 72 + n], Vb[(kb + t + 4) * 72 + n] };
                mma_tf32(acc[nf], a, bb);
            }
        }
        __syncthreads();
    }

    // Write tf32 bits: row = b*SEQ + q, col = h*64 + d
    const float il_lo = 1.0f / l_lo;
    const float il_hi = 1.0f / l_hi;
    const size_t row0 = (size_t)b * SEQ + q0 + mrow;
#pragma unroll
    for (int nf = 0; nf < 8; nf++) {
        const int c = h * DH + nf * 8 + t * 2;
        uint2 o0 = { f2tf32(acc[nf][0] * il_lo), f2tf32(acc[nf][1] * il_lo) };
        uint2 o1 = { f2tf32(acc[nf][2] * il_hi), f2tf32(acc[nf][3] * il_hi) };
        *(uint2*)(out + row0 * DATT + c) = o0;
        *(uint2*)(out + (row0 + 8) * DATT + c) = o1;
    }
#undef ISSUE_KV
}

// ---------------------------------------------------------------------------
extern "C" void kernel_launch(void* const* d_in, const int* in_sizes, int n_in,
                              void* d_out, int out_size)
{
    const float* x     = (const float*)d_in[0];
    const float* w_in  = (const float*)d_in[1];
    const float* b_in  = (const float*)d_in[2];
    const float* w_out = (const float*)d_in[3];
    const float* b_out = (const float*)d_in[4];
    float* out = (float*)d_out;

    uint32_t *xt, *wint, *woutt, *qkv, *attn;
    cudaGetSymbolAddress((void**)&xt,    g_xt);
    cudaGetSymbolAddress((void**)&wint,  g_wint);
    cudaGetSymbolAddress((void**)&woutt, g_woutt);
    cudaGetSymbolAddress((void**)&qkv,   g_qkv);
    cudaGetSymbolAddress((void**)&attn,  g_attn);

    cudaFuncSetAttribute(gemm_tf32_pipe, cudaFuncAttributeMaxDynamicSharedMemorySize, GEMM_SMEM);
    cudaFuncSetAttribute(attn_tf32_pipe, cudaFuncAttributeMaxDynamicSharedMemorySize, ATT_SMEM);

    // 0) pre-convert inputs to tf32
    cvt_tf32<<<(MROWS * DE / 4) / 256, 256>>>((const float4*)x, (uint4*)xt);
    cvt_tf32<<<(DE * TRIPLE / 4) / 256, 256>>>((const float4*)w_in, (uint4*)wint);
    cvt_tf32<<<(DATT * DE / 4) / 256, 256>>>((const float4*)w_out, (uint4*)woutt);

    // 1) QKV = x @ w_in + b_in  -> tf32 qkv in (which,b,h,s,d)
    dim3 g1(TRIPLE / 128, MROWS / 128);
    gemm_tf32_pipe<<<g1, 256, GEMM_SMEM>>>(xt, wint, b_in, qkv, MROWS, TRIPLE, DE, 1);

    // 2) attention -> tf32 attn
    dim3 g2(SEQ / 128, NH, BATCH);
    attn_tf32_pipe<<<g2, 256, ATT_SMEM>>>(qkv, attn);

    // 3) out = attn @ w_out + b_out (fp32)
    dim3 g3(DE / 128, MROWS / 128);
    gemm_tf32_pipe<<<g3, 256, GEMM_SMEM>>>(attn, woutt, b_out, out, MROWS, DE, DATT, 0);
}